// round 12
// baseline (speedup 1.0000x reference)
#include <cuda_runtime.h>
#include <cuda_fp16.h>
#include <cstdint>

// Problem constants
#define H      2048
#define EI     1024
#define NE     8
#define NT     2048
#define NVOCAB 32000

// GEMM tiling: 128 x 64 tile, BK = 32 k per stage, 8 warps (2M x 4N)
#define BM 128
#define BN 64
#define BK 32

// smem per f32 stage: A fp16 [128][32] stride 80B, B f32 [32][64] stride 272B
#define AROWB 80
#define BROWB 272
#define BHROWB 144                        // fp16 B [32][64] stride 72 halves
#define A_BYTES (128 * AROWB)             // 10240
#define B_BYTES (32 * BROWB)              // 8704
#define BH_BYTES (32 * BHROWB)            // 4608
#define NSTAGE 4
#define A_OFF   0
#define BF_OFF  (NSTAGE * A_BYTES)        // 40960
#define BH_OFF  (BF_OFF + NSTAGE * B_BYTES)   // 75776
#define TOK_OFF (BH_OFF + 2 * BH_BYTES)   // 84992
#define SMEM_BYTES (TOK_OFF + BM * 4)     // 85504 -> 2 CTAs/SM

// Scratch (20 MB)
__device__ __half g_xh[(size_t)NT * H];
__device__ __half g_gu[(size_t)NT * H];
__device__ __half g_h[(size_t)NT * EI];
__device__ int    g_perm[NT];
__device__ int    g_cnt[NE];
__device__ int    g_off[NE];

// ---------------------------------------------------------------------------
// helpers
// ---------------------------------------------------------------------------
__device__ __forceinline__ float silu(float x) { return x / (1.0f + __expf(-x)); }

__device__ __forceinline__ void cp_async16(void* dst_smem, const void* src) {
    uint32_t dst = (uint32_t)__cvta_generic_to_shared(dst_smem);
    asm volatile("cp.async.cg.shared.global [%0], [%1], 16;\n" :: "r"(dst), "l"(src));
}
#define CP_COMMIT() asm volatile("cp.async.commit_group;\n")
#define CP_WAIT(n)  asm volatile("cp.async.wait_group %0;\n" :: "n"(n))

__device__ __forceinline__ void mma_f16(float* d, const uint32_t* a, const uint32_t* b) {
    asm volatile(
        "mma.sync.aligned.m16n8k16.row.col.f32.f16.f16.f32 "
        "{%0,%1,%2,%3}, {%4,%5,%6,%7}, {%8,%9}, {%0,%1,%2,%3};"
        : "+f"(d[0]), "+f"(d[1]), "+f"(d[2]), "+f"(d[3])
        : "r"(a[0]), "r"(a[1]), "r"(a[2]), "r"(a[3]), "r"(b[0]), "r"(b[1]));
}

__device__ __forceinline__ void ldsm_x4(uint32_t* r, uint32_t addr) {
    asm volatile("ldmatrix.sync.aligned.m8n8.x4.shared.b16 {%0,%1,%2,%3}, [%4];"
                 : "=r"(r[0]), "=r"(r[1]), "=r"(r[2]), "=r"(r[3]) : "r"(addr));
}
__device__ __forceinline__ void ldsm_x4_t(uint32_t* r, uint32_t addr) {
    asm volatile("ldmatrix.sync.aligned.m8n8.x4.trans.shared.b16 {%0,%1,%2,%3}, [%4];"
                 : "=r"(r[0]), "=r"(r[1]), "=r"(r[2]), "=r"(r[3]) : "r"(addr));
}

__device__ __forceinline__ uint32_t pack2h(float lo, float hi) {
    __half2 h = __floats2half2_rn(lo, hi);
    return *reinterpret_cast<uint32_t*>(&h);
}

// ---------------------------------------------------------------------------
// prep: blocks [0, NXB) convert x -> fp16; block NXB does routing.
// ---------------------------------------------------------------------------
#define RT_THREADS 256
#define RT_PER_THR (NT / RT_THREADS)
#define NXB ((NT * H / 8) / 256)

__global__ void prep_kernel(const float* __restrict__ x,
                            const int* __restrict__ token_ids) {
    if (blockIdx.x < NXB) {
        size_t i = ((size_t)blockIdx.x * 256 + threadIdx.x) * 8;
        float4 v0 = *reinterpret_cast<const float4*>(x + i);
        float4 v1 = *reinterpret_cast<const float4*>(x + i + 4);
        uint4 u;
        u.x = pack2h(v0.x, v0.y);
        u.y = pack2h(v0.z, v0.w);
        u.z = pack2h(v1.x, v1.y);
        u.w = pack2h(v1.z, v1.w);
        *reinterpret_cast<uint4*>(g_xh + i) = u;
        return;
    }

    __shared__ int s_hist[RT_THREADS][NE];
    __shared__ int s_pre[RT_THREADS][NE];
    __shared__ int s_total[NE];
    __shared__ int s_exoff[NE];

    const int tid = threadIdx.x;
    const int warp = tid >> 5, lane = tid & 31;

    int loc[NE];
#pragma unroll
    for (int e = 0; e < NE; e++) loc[e] = 0;
    int eid[RT_PER_THR];
#pragma unroll
    for (int i = 0; i < RT_PER_THR; i++) {
        int id = token_ids[tid * RT_PER_THR + i];
        id = min(max(id, 0), NVOCAB - 1);
        int e = id & (NE - 1);
        eid[i] = e;
        loc[e]++;
    }
#pragma unroll
    for (int e = 0; e < NE; e++) s_hist[tid][e] = loc[e];
    __syncthreads();

    if (warp < NE) {
        const int e = warp;
        int run = 0;
        for (int c = 0; c < RT_THREADS; c += 32) {
            int orig = s_hist[c + lane][e];
            int v = orig;
#pragma unroll
            for (int d = 1; d < 32; d <<= 1) {
                int n = __shfl_up_sync(0xFFFFFFFFu, v, d);
                if (lane >= d) v += n;
            }
            s_pre[c + lane][e] = run + v - orig;
            run += __shfl_sync(0xFFFFFFFFu, v, 31);
        }
        if (lane == 31) s_total[e] = run;
    }
    __syncthreads();
    if (tid == 0) {
        int off = 0;
        for (int e = 0; e < NE; e++) {
            s_exoff[e] = off;
            g_off[e] = off;
            g_cnt[e] = s_total[e];
            off += s_total[e];
        }
    }
    __syncthreads();
    int cur[NE];
#pragma unroll
    for (int e = 0; e < NE; e++) cur[e] = s_exoff[e] + s_pre[tid][e];
#pragma unroll
    for (int i = 0; i < RT_PER_THR; i++) {
        int e = eid[i];
        g_perm[cur[e]++] = tid * RT_PER_THR + i;
    }
}

// ---------------------------------------------------------------------------
// Activation: g_h = fp16(silu(gate) * up), reading fp16 g_gu
// ---------------------------------------------------------------------------
__global__ __launch_bounds__(256)
void act_kernel() {
    int idx = blockIdx.x * blockDim.x + threadIdx.x;
    int row = idx / (EI / 4);
    int c   = (idx % (EI / 4)) * 4;
    const __half* gu = g_gu + (size_t)row * H;
    uint2 gp = *reinterpret_cast<const uint2*>(gu + c);
    uint2 up = *reinterpret_cast<const uint2*>(gu + c + EI);
    float2 g0 = __half22float2(*reinterpret_cast<__half2*>(&gp.x));
    float2 g1 = __half22float2(*reinterpret_cast<__half2*>(&gp.y));
    float2 u0 = __half22float2(*reinterpret_cast<__half2*>(&up.x));
    float2 u1 = __half22float2(*reinterpret_cast<__half2*>(&up.y));
    uint2 o;
    o.x = pack2h(silu(g0.x) * u0.x, silu(g0.y) * u0.y);
    o.y = pack2h(silu(g1.x) * u1.x, silu(g1.y) * u1.y);
    *reinterpret_cast<uint2*>(g_h + (size_t)row * EI + c) = o;
}

// ---------------------------------------------------------------------------
// GEMM body: C[128,64] = A(fp16) @ W[K][N] (f32 staged; converted to fp16 in
// smem cooperatively; fragments via ldmatrix / ldmatrix.trans).
// Per iter: CP_WAIT (pre-barrier) -> barrier -> stage(kt+3) -> convert(kt+1)
// -> compute(kt).
// ---------------------------------------------------------------------------
#define TC_GEMM_BODY(A_SRC_ROW, WP, LDN, KTOT, EPILOGUE)                            \
    extern __shared__ char smc[];                                                   \
    int* s_tok = (int*)(smc + TOK_OFF);                                             \
    const int tid = threadIdx.x;                                                    \
    if (tid < BM) s_tok[tid] = g_perm[min(base + m0 + tid, NT - 1)];                \
    __syncthreads();                                                                \
    const int warp = tid >> 5, lane = tid & 31;                                     \
    const int wm = (warp & 1) * 64;                                                 \
    const int wn = (warp >> 1) * 16;                                                \
    const int grp = lane >> 2, quad = lane & 3;                                     \
    const int a_row = tid >> 2, a_ch = tid & 3;                                     \
    const int b_row = tid >> 4, b_ch = tid & 15;                                    \
    const int lm_row = wm + (lane & 15);                                            \
    const int lm_col = (lane >> 4) * 16;                                            \
    const int bt_row = (lane & 7) + ((lane >> 3) & 1) * 8;                          \
    const int bt_col = (wn + (lane >> 4) * 8) * 2;                                  \
    const int cv_k = tid >> 3, cv_c = (tid & 7) * 8;                                \
    float acc[4][2][4];                                                             \
    _Pragma("unroll")                                                               \
    for (int i = 0; i < 4; i++)                                                     \
        _Pragma("unroll")                                                           \
        for (int j = 0; j < 2; j++)                                                 \
            _Pragma("unroll")                                                       \
            for (int r = 0; r < 4; r++) acc[i][j][r] = 0.f;                         \
    auto stage = [&](int kt0, int buf) {                                            \
        char* sa = smc + A_OFF + buf * A_BYTES;                                     \
        char* sb = smc + BF_OFF + buf * B_BYTES;                                    \
        _Pragma("unroll")                                                           \
        for (int i = 0; i < 2; i++) {                                               \
            int row = a_row + i * 64;                                               \
            cp_async16(sa + row * AROWB + a_ch * 16,                                \
                       A_SRC_ROW(row) + kt0 + a_ch * 8);                            \
        }                                                                           \
        _Pragma("unroll")                                                           \
        for (int i = 0; i < 2; i++) {                                               \
            int k = b_row + i * 16;                                                 \
            cp_async16(sb + k * BROWB + b_ch * 16,                                  \
                       (WP) + (size_t)(kt0 + k) * (LDN) + n0 + b_ch * 4);           \
        }                                                                           \
        CP_COMMIT();                                                                \
    };                                                                              \
    auto convb = [&](int srcbuf, int dstbuf) {                                      \
        const float* sf = (const float*)(smc + BF_OFF + srcbuf * B_BYTES)           \
                          + cv_k * 68 + cv_c;                                       \
        float4 v0 = *reinterpret_cast<const float4*>(sf);                           \
        float4 v1 = *reinterpret_cast<const float4*>(sf + 4);                       \
        uint4 o;                                                                    \
        o.x = pack2h(v0.x, v0.y);                                                   \
        o.y = pack2h(v0.z, v0.w);                                                   \
        o.z = pack2h(v1.x, v1.y);                                                   \
        o.w = pack2h(v1.z, v1.w);                                                   \
        *reinterpret_cast<uint4*>(smc + BH_OFF + dstbuf * BH_BYTES                  \
                                  + cv_k * BHROWB + cv_c * 2) = o;                  \
    };                                                                              \
    const int KT = (KTOT) / BK;                                                     \
    stage(0, 0); stage(BK, 1); stage(2 * BK, 2);                                    \
    CP_WAIT(2);                                                                     \
    __syncthreads();                                                                \
    convb(0, 0);                                                                    \
    for (int kt = 0; kt < KT; kt++) {                                               \
        if (kt < KT - 3) { CP_WAIT(1); } else { CP_WAIT(0); }                       \
        __syncthreads();                                                            \
        if (kt + 3 < KT) stage((kt + 3) * BK, (kt + 3) & 3);                        \
        if (kt + 1 < KT) convb((kt + 1) & 3, (kt + 1) & 1);                         \
        const uint32_t sa_u = (uint32_t)__cvta_generic_to_shared(                   \
            smc + A_OFF + (kt & 3) * A_BYTES);                                      \
        const uint32_t sbh_u = (uint32_t)__cvta_generic_to_shared(                  \
            smc + BH_OFF + (kt & 1) * BH_BYTES);                                    \
        _Pragma("unroll")                                                           \
        for (int ks = 0; ks < 2; ks++) {                                            \
            uint32_t af[4][4], bt[4];                                               \
            ldsm_x4_t(bt, sbh_u + (uint32_t)((ks * 16 + bt_row) * BHROWB + bt_col));\
            _Pragma("unroll")                                                       \
            for (int mf = 0; mf < 4; mf++)                                          \
                ldsm_x4(af[mf], sa_u + (uint32_t)((lm_row + mf * 16) * AROWB        \
                                                  + ks * 32 + lm_col));             \
            _Pragma("unroll")                                                       \
            for (int mf = 0; mf < 4; mf++) {                                        \
                mma_f16(acc[mf][0], af[mf], bt);                                    \
                mma_f16(acc[mf][1], af[mf], bt + 2);                                \
            }                                                                       \
        }                                                                           \
    }                                                                               \
    const int mrem = cnt - m0;                                                      \
    _Pragma("unroll")                                                               \
    for (int mf = 0; mf < 4; mf++) {                                                \
        int r0 = wm + mf * 16 + grp;                                                \
        int r1 = r0 + 8;                                                            \
        _Pragma("unroll")                                                           \
        for (int nf = 0; nf < 2; nf++) {                                            \
            int c = n0 + wn + nf * 8 + quad * 2;                                    \
            EPILOGUE                                                                \
        }                                                                           \
    }

// GEMM1: g_gu[base+m0+r, :] = xh(token rows) @ gate_up[e]   (K=H, N=2*EI)
__global__ __launch_bounds__(256, 2)
void gemm1_kernel(const float* __restrict__ gate_up) {
    const int e   = blockIdx.z;
    const int cnt = g_cnt[e];
    const int m0  = blockIdx.y * BM;
    if (m0 >= cnt) return;
    const int base = g_off[e];
    const int n0   = blockIdx.x * BN;
    const float* Wp = gate_up + (size_t)e * H * (2 * EI);

#define A1_SRC(row) (g_xh + (size_t)s_tok[row] * H)
#define EPI1                                                                        \
    if (r0 < mrem)                                                                  \
        *reinterpret_cast<uint32_t*>(&g_gu[(size_t)(base + m0 + r0) * H + c]) =     \
            pack2h(acc[mf][nf][0], acc[mf][nf][1]);                                 \
    if (r1 < mrem)                                                                  \
        *reinterpret_cast<uint32_t*>(&g_gu[(size_t)(base + m0 + r1) * H + c]) =     \
            pack2h(acc[mf][nf][2], acc[mf][nf][3]);

    TC_GEMM_BODY(A1_SRC, Wp, 2 * EI, H, EPI1)
#undef A1_SRC
#undef EPI1
}

// GEMM2: out[tok, :] = g_h(sorted rows) @ down[e]   (K=EI, N=H)
__global__ __launch_bounds__(256, 2)
void gemm2_kernel(const float* __restrict__ down, float* __restrict__ out) {
    const int e   = blockIdx.z;
    const int cnt = g_cnt[e];
    const int m0  = blockIdx.y * BM;
    if (m0 >= cnt) return;
    const int base = g_off[e];
    const int n0   = blockIdx.x * BN;
    const float* Wp = down + (size_t)e * EI * H;

#define A2_SRC(row) (g_h + (size_t)min(base + m0 + (row), NT - 1) * EI)
#define EPI2                                                                        \
    if (r0 < mrem)                                                                  \
        *reinterpret_cast<float2*>(&out[(size_t)s_tok[r0] * H + c]) =               \
            make_float2(acc[mf][nf][0], acc[mf][nf][1]);                            \
    if (r1 < mrem)                                                                  \
        *reinterpret_cast<float2*>(&out[(size_t)s_tok[r1] * H + c]) =               \
            make_float2(acc[mf][nf][2], acc[mf][nf][3]);

    TC_GEMM_BODY(A2_SRC, Wp, H, EI, EPI2)
#undef A2_SRC
#undef EPI2
}

// ---------------------------------------------------------------------------
// Launch
// ---------------------------------------------------------------------------
extern "C" void kernel_launch(void* const* d_in, const int* in_sizes, int n_in,
                              void* d_out, int out_size) {
    const float* x         = (const float*)d_in[0];
    const int*   token_ids = (const int*)d_in[1];
    const float* gate_up   = (const float*)d_in[2];
    const float* down      = (const float*)d_in[3];
    float*       out       = (float*)d_out;

    cudaFuncSetAttribute(gemm1_kernel, cudaFuncAttributeMaxDynamicSharedMemorySize, SMEM_BYTES);
    cudaFuncSetAttribute(gemm2_kernel, cudaFuncAttributeMaxDynamicSharedMemorySize, SMEM_BYTES);

    prep_kernel<<<NXB + 1, 256>>>(x, token_ids);

    dim3 grid1(2 * EI / BN, NT / BM, NE);
    gemm1_kernel<<<grid1, 256, SMEM_BYTES>>>(gate_up);
    act_kernel<<<(NT * EI / 4) / 256, 256>>>();
    dim3 grid2(H / BN, NT / BM, NE);
    gemm2_kernel<<<grid2, 256, SMEM_BYTES>>>(down, out);
}

// round 13
// speedup vs baseline: 1.1329x; 1.1329x over previous
#include <cuda_runtime.h>
#include <cuda_fp16.h>
#include <cstdint>

// Problem constants
#define H      2048
#define EI     1024
#define NE     8
#define NT     2048
#define NVOCAB 32000

// GEMM tiling: 256 x 64 tile, BK = 32, 8 warps as 4M x 2N (warp tile 64x32)
#define BM 256
#define BN 64
#define BK 32

// smem per stage: A fp16 [256][32] stride 80B, B f32 [32][64] stride 272B
#define AROWB 80
#define BROWB 272
#define A_BYTES (256 * AROWB)            // 20480
#define B_BYTES (32 * BROWB)             // 8704
#define STAGE_BYTES (A_BYTES + B_BYTES)  // 29184
#define NSTAGE 3
#define TOK_OFF (NSTAGE * STAGE_BYTES)   // 87552
#define SMEM_BYTES (TOK_OFF + BM * 4)    // 88576 -> 2 CTAs/SM

// Scratch (20 MB)
__device__ __half g_xh[(size_t)NT * H];
__device__ __half g_gu[(size_t)NT * H];
__device__ __half g_h[(size_t)NT * EI];
__device__ int    g_perm[NT];
__device__ int    g_cnt[NE];
__device__ int    g_off[NE];

// ---------------------------------------------------------------------------
// helpers
// ---------------------------------------------------------------------------
__device__ __forceinline__ float silu(float x) { return x / (1.0f + __expf(-x)); }

__device__ __forceinline__ void cp_async16(void* dst_smem, const void* src) {
    uint32_t dst = (uint32_t)__cvta_generic_to_shared(dst_smem);
    asm volatile("cp.async.cg.shared.global [%0], [%1], 16;\n" :: "r"(dst), "l"(src));
}
#define CP_COMMIT() asm volatile("cp.async.commit_group;\n")
#define CP_WAIT(n)  asm volatile("cp.async.wait_group %0;\n" :: "n"(n))

__device__ __forceinline__ void mma_f16(float* d, const uint32_t* a, const uint32_t* b) {
    asm volatile(
        "mma.sync.aligned.m16n8k16.row.col.f32.f16.f16.f32 "
        "{%0,%1,%2,%3}, {%4,%5,%6,%7}, {%8,%9}, {%0,%1,%2,%3};"
        : "+f"(d[0]), "+f"(d[1]), "+f"(d[2]), "+f"(d[3])
        : "r"(a[0]), "r"(a[1]), "r"(a[2]), "r"(a[3]), "r"(b[0]), "r"(b[1]));
}

__device__ __forceinline__ void ldsm_x4(uint32_t* r, uint32_t addr) {
    asm volatile("ldmatrix.sync.aligned.m8n8.x4.shared.b16 {%0,%1,%2,%3}, [%4];"
                 : "=r"(r[0]), "=r"(r[1]), "=r"(r[2]), "=r"(r[3]) : "r"(addr));
}

__device__ __forceinline__ uint32_t pack2h(float lo, float hi) {
    __half2 h = __floats2half2_rn(lo, hi);
    return *reinterpret_cast<uint32_t*>(&h);
}

// ---------------------------------------------------------------------------
// prep: blocks [0, NXB) convert x -> fp16; block NXB does routing.
// ---------------------------------------------------------------------------
#define RT_THREADS 256
#define RT_PER_THR (NT / RT_THREADS)
#define NXB ((NT * H / 8) / 256)

__global__ void prep_kernel(const float* __restrict__ x,
                            const int* __restrict__ token_ids) {
    if (blockIdx.x < NXB) {
        size_t i = ((size_t)blockIdx.x * 256 + threadIdx.x) * 8;
        float4 v0 = *reinterpret_cast<const float4*>(x + i);
        float4 v1 = *reinterpret_cast<const float4*>(x + i + 4);
        uint4 u;
        u.x = pack2h(v0.x, v0.y);
        u.y = pack2h(v0.z, v0.w);
        u.z = pack2h(v1.x, v1.y);
        u.w = pack2h(v1.z, v1.w);
        *reinterpret_cast<uint4*>(g_xh + i) = u;
        return;
    }

    __shared__ int s_hist[RT_THREADS][NE];
    __shared__ int s_pre[RT_THREADS][NE];
    __shared__ int s_total[NE];
    __shared__ int s_exoff[NE];

    const int tid = threadIdx.x;
    const int warp = tid >> 5, lane = tid & 31;

    int loc[NE];
#pragma unroll
    for (int e = 0; e < NE; e++) loc[e] = 0;
    int eid[RT_PER_THR];
#pragma unroll
    for (int i = 0; i < RT_PER_THR; i++) {
        int id = token_ids[tid * RT_PER_THR + i];
        id = min(max(id, 0), NVOCAB - 1);
        int e = id & (NE - 1);
        eid[i] = e;
        loc[e]++;
    }
#pragma unroll
    for (int e = 0; e < NE; e++) s_hist[tid][e] = loc[e];
    __syncthreads();

    if (warp < NE) {
        const int e = warp;
        int run = 0;
        for (int c = 0; c < RT_THREADS; c += 32) {
            int orig = s_hist[c + lane][e];
            int v = orig;
#pragma unroll
            for (int d = 1; d < 32; d <<= 1) {
                int n = __shfl_up_sync(0xFFFFFFFFu, v, d);
                if (lane >= d) v += n;
            }
            s_pre[c + lane][e] = run + v - orig;
            run += __shfl_sync(0xFFFFFFFFu, v, 31);
        }
        if (lane == 31) s_total[e] = run;
    }
    __syncthreads();
    if (tid == 0) {
        int off = 0;
        for (int e = 0; e < NE; e++) {
            s_exoff[e] = off;
            g_off[e] = off;
            g_cnt[e] = s_total[e];
            off += s_total[e];
        }
    }
    __syncthreads();
    int cur[NE];
#pragma unroll
    for (int e = 0; e < NE; e++) cur[e] = s_exoff[e] + s_pre[tid][e];
#pragma unroll
    for (int i = 0; i < RT_PER_THR; i++) {
        int e = eid[i];
        g_perm[cur[e]++] = tid * RT_PER_THR + i;
    }
}

// ---------------------------------------------------------------------------
// Activation: g_h = fp16(silu(gate) * up), reading fp16 g_gu
// ---------------------------------------------------------------------------
__global__ __launch_bounds__(256)
void act_kernel() {
    int idx = blockIdx.x * blockDim.x + threadIdx.x;
    int row = idx / (EI / 4);
    int c   = (idx % (EI / 4)) * 4;
    const __half* gu = g_gu + (size_t)row * H;
    uint2 gp = *reinterpret_cast<const uint2*>(gu + c);
    uint2 up = *reinterpret_cast<const uint2*>(gu + c + EI);
    float2 g0 = __half22float2(*reinterpret_cast<__half2*>(&gp.x));
    float2 g1 = __half22float2(*reinterpret_cast<__half2*>(&gp.y));
    float2 u0 = __half22float2(*reinterpret_cast<__half2*>(&up.x));
    float2 u1 = __half22float2(*reinterpret_cast<__half2*>(&up.y));
    uint2 o;
    o.x = pack2h(silu(g0.x) * u0.x, silu(g0.y) * u0.y);
    o.y = pack2h(silu(g1.x) * u1.x, silu(g1.y) * u1.y);
    *reinterpret_cast<uint2*>(g_h + (size_t)row * EI + c) = o;
}

// ---------------------------------------------------------------------------
// GEMM body: C[256,64] = A(fp16 rows) @ W[K][N] (f32 streamed, fragment-pack)
// 3-stage pipeline; stage issued AFTER the barrier (round-10 proven skeleton).
// Warp layout 4M x 2N; A fragments via ldmatrix.x4, B via scalar LDS + pack.
// ---------------------------------------------------------------------------
#define TC_GEMM_BODY(A_SRC_ROW, WP, LDN, KTOT, EPILOGUE)                            \
    extern __shared__ char smc[];                                                   \
    int* s_tok = (int*)(smc + TOK_OFF);                                             \
    const int tid = threadIdx.x;                                                    \
    s_tok[tid] = g_perm[min(base + m0 + tid, NT - 1)];                              \
    __syncthreads();                                                                \
    const int warp = tid >> 5, lane = tid & 31;                                     \
    const int wm = (warp >> 1) * 64;                                                \
    const int wn = (warp & 1) * 32;                                                 \
    const int grp = lane >> 2, quad = lane & 3;                                     \
    const int a_row = tid >> 2, a_ch = tid & 3;                                     \
    const int b_row = tid >> 4, b_ch = tid & 15;                                    \
    const int lm_row = wm + (lane & 15);                                            \
    const int lm_col = (lane >> 4) * 16;                                            \
    float acc[4][4][4];                                                             \
    _Pragma("unroll")                                                               \
    for (int i = 0; i < 4; i++)                                                     \
        _Pragma("unroll")                                                           \
        for (int j = 0; j < 4; j++)                                                 \
            _Pragma("unroll")                                                       \
            for (int r = 0; r < 4; r++) acc[i][j][r] = 0.f;                         \
    auto stage = [&](int kt0, int buf) {                                            \
        char* sa = smc + buf * STAGE_BYTES;                                         \
        char* sb = sa + A_BYTES;                                                    \
        _Pragma("unroll")                                                           \
        for (int i = 0; i < 4; i++) {                                               \
            int row = a_row + i * 64;                                               \
            cp_async16(sa + row * AROWB + a_ch * 16,                                \
                       A_SRC_ROW(row) + kt0 + a_ch * 8);                            \
        }                                                                           \
        _Pragma("unroll")                                                           \
        for (int i = 0; i < 2; i++) {                                               \
            int k = b_row + i * 16;                                                 \
            cp_async16(sb + k * BROWB + b_ch * 16,                                  \
                       (WP) + (size_t)(kt0 + k) * (LDN) + n0 + b_ch * 4);           \
        }                                                                           \
        CP_COMMIT();                                                                \
    };                                                                              \
    const int KT = (KTOT) / BK;                                                     \
    stage(0, 0); stage(BK, 1);                                                      \
    for (int kt = 0; kt < KT; kt++) {                                               \
        if (kt + 1 < KT) { CP_WAIT(1); } else { CP_WAIT(0); }                       \
        __syncthreads();                                                            \
        if (kt + 2 < KT) stage((kt + 2) * BK, (kt + 2) % NSTAGE);                   \
        const char*  sa  = smc + (kt % NSTAGE) * STAGE_BYTES;                       \
        const float* sbf = (const float*)(sa + A_BYTES);                            \
        const uint32_t sa_u = (uint32_t)__cvta_generic_to_shared(sa);               \
        _Pragma("unroll")                                                           \
        for (int ks = 0; ks < 2; ks++) {                                            \
            uint32_t af[4][4], bf[4][2];                                            \
            _Pragma("unroll")                                                       \
            for (int mf = 0; mf < 4; mf++)                                          \
                ldsm_x4(af[mf], sa_u + (uint32_t)((lm_row + mf * 16) * AROWB        \
                                                  + ks * 32 + lm_col));             \
            _Pragma("unroll")                                                       \
            for (int nf = 0; nf < 4; nf++) {                                        \
                int n  = wn + nf * 8 + grp;                                         \
                int k0 = ks * 16 + quad * 2;                                        \
                bf[nf][0] = pack2h(sbf[(size_t)k0 * 68 + n],                        \
                                   sbf[(size_t)(k0 + 1) * 68 + n]);                 \
                bf[nf][1] = pack2h(sbf[(size_t)(k0 + 8) * 68 + n],                  \
                                   sbf[(size_t)(k0 + 9) * 68 + n]);                 \
            }                                                                       \
            _Pragma("unroll")                                                       \
            for (int mf = 0; mf < 4; mf++)                                          \
                _Pragma("unroll")                                                   \
                for (int nf = 0; nf < 4; nf++)                                      \
                    mma_f16(acc[mf][nf], af[mf], bf[nf]);                           \
        }                                                                           \
    }                                                                               \
    const int mrem = cnt - m0;                                                      \
    _Pragma("unroll")                                                               \
    for (int mf = 0; mf < 4; mf++) {                                                \
        int r0 = wm + mf * 16 + grp;                                                \
        int r1 = r0 + 8;                                                            \
        _Pragma("unroll")                                                           \
        for (int nf = 0; nf < 4; nf++) {                                            \
            int c = n0 + wn + nf * 8 + quad * 2;                                    \
            EPILOGUE                                                                \
        }                                                                           \
    }

// GEMM1: g_gu[base+m0+r, :] = xh(token rows) @ gate_up[e]   (K=H, N=2*EI)
__global__ __launch_bounds__(256, 2)
void gemm1_kernel(const float* __restrict__ gate_up) {
    const int e   = blockIdx.z;
    const int cnt = g_cnt[e];
    const int m0  = blockIdx.y * BM;
    if (m0 >= cnt) return;
    const int base = g_off[e];
    const int n0   = blockIdx.x * BN;
    const float* Wp = gate_up + (size_t)e * H * (2 * EI);

#define A1_SRC(row) (g_xh + (size_t)s_tok[row] * H)
#define EPI1                                                                        \
    if (r0 < mrem)                                                                  \
        *reinterpret_cast<uint32_t*>(&g_gu[(size_t)(base + m0 + r0) * H + c]) =     \
            pack2h(acc[mf][nf][0], acc[mf][nf][1]);                                 \
    if (r1 < mrem)                                                                  \
        *reinterpret_cast<uint32_t*>(&g_gu[(size_t)(base + m0 + r1) * H + c]) =     \
            pack2h(acc[mf][nf][2], acc[mf][nf][3]);

    TC_GEMM_BODY(A1_SRC, Wp, 2 * EI, H, EPI1)
#undef A1_SRC
#undef EPI1
}

// GEMM2: out[tok, :] = g_h(sorted rows) @ down[e]   (K=EI, N=H)
__global__ __launch_bounds__(256, 2)
void gemm2_kernel(const float* __restrict__ down, float* __restrict__ out) {
    const int e   = blockIdx.z;
    const int cnt = g_cnt[e];
    const int m0  = blockIdx.y * BM;
    if (m0 >= cnt) return;
    const int base = g_off[e];
    const int n0   = blockIdx.x * BN;
    const float* Wp = down + (size_t)e * EI * H;

#define A2_SRC(row) (g_h + (size_t)min(base + m0 + (row), NT - 1) * EI)
#define EPI2                                                                        \
    if (r0 < mrem)                                                                  \
        *reinterpret_cast<float2*>(&out[(size_t)s_tok[r0] * H + c]) =               \
            make_float2(acc[mf][nf][0], acc[mf][nf][1]);                            \
    if (r1 < mrem)                                                                  \
        *reinterpret_cast<float2*>(&out[(size_t)s_tok[r1] * H + c]) =               \
            make_float2(acc[mf][nf][2], acc[mf][nf][3]);

    TC_GEMM_BODY(A2_SRC, Wp, H, EI, EPI2)
#undef A2_SRC
#undef EPI2
}

// ---------------------------------------------------------------------------
// Launch
// ---------------------------------------------------------------------------
extern "C" void kernel_launch(void* const* d_in, const int* in_sizes, int n_in,
                              void* d_out, int out_size) {
    const float* x         = (const float*)d_in[0];
    const int*   token_ids = (const int*)d_in[1];
    const float* gate_up   = (const float*)d_in[2];
    const float* down      = (const float*)d_in[3];
    float*       out       = (float*)d_out;

    cudaFuncSetAttribute(gemm1_kernel, cudaFuncAttributeMaxDynamicSharedMemorySize, SMEM_BYTES);
    cudaFuncSetAttribute(gemm2_kernel, cudaFuncAttributeMaxDynamicSharedMemorySize, SMEM_BYTES);

    prep_kernel<<<NXB + 1, 256>>>(x, token_ids);

    dim3 grid1(2 * EI / BN, (NT + BM - 1) / BM, NE);   // 32 x 8 x 8
    gemm1_kernel<<<grid1, 256, SMEM_BYTES>>>(gate_up);
    act_kernel<<<(NT * EI / 4) / 256, 256>>>();
    dim3 grid2(H / BN, (NT + BM - 1) / BM, NE);        // 32 x 8 x 8
    gemm2_kernel<<<grid2, 256, SMEM_BYTES>>>(down, out);
}

// round 14
// speedup vs baseline: 1.2203x; 1.0772x over previous
#include <cuda_runtime.h>
#include <cuda_fp16.h>
#include <cstdint>

// Problem constants
#define H      2048
#define EI     1024
#define NE     8
#define NT     2048
#define NVOCAB 32000

// GEMM tiling: 128 x 64 tile, BK = 64 k per stage, 8 warps (2M x 4N)
#define BM 128
#define BN 64
#define BK 64

// smem per stage: A fp16 [128][64] stride 144B, B f32 [64][64] stride 272B
#define AROWB 144
#define BROWB 272
#define A_BYTES (128 * AROWB)            // 18432
#define B_BYTES (64 * BROWB)             // 17408
#define STAGE_BYTES (A_BYTES + B_BYTES)  // 35840
#define NSTAGE 3
#define TOK_OFF (NSTAGE * STAGE_BYTES)   // 107520
#define SMEM_BYTES (TOK_OFF + BM * 4)    // 108032 -> 2 CTAs/SM (216KB/SM)

// Scratch (20 MB)
__device__ __half g_xh[(size_t)NT * H];
__device__ __half g_gu[(size_t)NT * H];
__device__ __half g_h[(size_t)NT * EI];
__device__ int    g_perm[NT];
__device__ int    g_cnt[NE];
__device__ int    g_off[NE];

// ---------------------------------------------------------------------------
// helpers
// ---------------------------------------------------------------------------
__device__ __forceinline__ float silu(float x) { return x / (1.0f + __expf(-x)); }

__device__ __forceinline__ void cp_async16(void* dst_smem, const void* src) {
    uint32_t dst = (uint32_t)__cvta_generic_to_shared(dst_smem);
    asm volatile("cp.async.cg.shared.global [%0], [%1], 16;\n" :: "r"(dst), "l"(src));
}
#define CP_COMMIT() asm volatile("cp.async.commit_group;\n")
#define CP_WAIT(n)  asm volatile("cp.async.wait_group %0;\n" :: "n"(n))

__device__ __forceinline__ void mma_f16(float* d, const uint32_t* a, const uint32_t* b) {
    asm volatile(
        "mma.sync.aligned.m16n8k16.row.col.f32.f16.f16.f32 "
        "{%0,%1,%2,%3}, {%4,%5,%6,%7}, {%8,%9}, {%0,%1,%2,%3};"
        : "+f"(d[0]), "+f"(d[1]), "+f"(d[2]), "+f"(d[3])
        : "r"(a[0]), "r"(a[1]), "r"(a[2]), "r"(a[3]), "r"(b[0]), "r"(b[1]));
}

__device__ __forceinline__ void ldsm_x4(uint32_t* r, uint32_t addr) {
    asm volatile("ldmatrix.sync.aligned.m8n8.x4.shared.b16 {%0,%1,%2,%3}, [%4];"
                 : "=r"(r[0]), "=r"(r[1]), "=r"(r[2]), "=r"(r[3]) : "r"(addr));
}

__device__ __forceinline__ uint32_t pack2h(float lo, float hi) {
    __half2 h = __floats2half2_rn(lo, hi);
    return *reinterpret_cast<uint32_t*>(&h);
}

// ---------------------------------------------------------------------------
// prep: blocks [0, NXB) convert x -> fp16; block NXB does routing.
// ---------------------------------------------------------------------------
#define RT_THREADS 256
#define RT_PER_THR (NT / RT_THREADS)
#define NXB ((NT * H / 8) / 256)

__global__ void prep_kernel(const float* __restrict__ x,
                            const int* __restrict__ token_ids) {
    if (blockIdx.x < NXB) {
        size_t i = ((size_t)blockIdx.x * 256 + threadIdx.x) * 8;
        float4 v0 = *reinterpret_cast<const float4*>(x + i);
        float4 v1 = *reinterpret_cast<const float4*>(x + i + 4);
        uint4 u;
        u.x = pack2h(v0.x, v0.y);
        u.y = pack2h(v0.z, v0.w);
        u.z = pack2h(v1.x, v1.y);
        u.w = pack2h(v1.z, v1.w);
        *reinterpret_cast<uint4*>(g_xh + i) = u;
        return;
    }

    __shared__ int s_hist[RT_THREADS][NE];
    __shared__ int s_pre[RT_THREADS][NE];
    __shared__ int s_total[NE];
    __shared__ int s_exoff[NE];

    const int tid = threadIdx.x;
    const int warp = tid >> 5, lane = tid & 31;

    int loc[NE];
#pragma unroll
    for (int e = 0; e < NE; e++) loc[e] = 0;
    int eid[RT_PER_THR];
#pragma unroll
    for (int i = 0; i < RT_PER_THR; i++) {
        int id = token_ids[tid * RT_PER_THR + i];
        id = min(max(id, 0), NVOCAB - 1);
        int e = id & (NE - 1);
        eid[i] = e;
        loc[e]++;
    }
#pragma unroll
    for (int e = 0; e < NE; e++) s_hist[tid][e] = loc[e];
    __syncthreads();

    if (warp < NE) {
        const int e = warp;
        int run = 0;
        for (int c = 0; c < RT_THREADS; c += 32) {
            int orig = s_hist[c + lane][e];
            int v = orig;
#pragma unroll
            for (int d = 1; d < 32; d <<= 1) {
                int n = __shfl_up_sync(0xFFFFFFFFu, v, d);
                if (lane >= d) v += n;
            }
            s_pre[c + lane][e] = run + v - orig;
            run += __shfl_sync(0xFFFFFFFFu, v, 31);
        }
        if (lane == 31) s_total[e] = run;
    }
    __syncthreads();
    if (tid == 0) {
        int off = 0;
        for (int e = 0; e < NE; e++) {
            s_exoff[e] = off;
            g_off[e] = off;
            g_cnt[e] = s_total[e];
            off += s_total[e];
        }
    }
    __syncthreads();
    int cur[NE];
#pragma unroll
    for (int e = 0; e < NE; e++) cur[e] = s_exoff[e] + s_pre[tid][e];
#pragma unroll
    for (int i = 0; i < RT_PER_THR; i++) {
        int e = eid[i];
        g_perm[cur[e]++] = tid * RT_PER_THR + i;
    }
}

// ---------------------------------------------------------------------------
// Activation: g_h = fp16(silu(gate) * up), reading fp16 g_gu
// ---------------------------------------------------------------------------
__global__ __launch_bounds__(256)
void act_kernel() {
    int idx = blockIdx.x * blockDim.x + threadIdx.x;
    int row = idx / (EI / 4);
    int c   = (idx % (EI / 4)) * 4;
    const __half* gu = g_gu + (size_t)row * H;
    uint2 gp = *reinterpret_cast<const uint2*>(gu + c);
    uint2 up = *reinterpret_cast<const uint2*>(gu + c + EI);
    float2 g0 = __half22float2(*reinterpret_cast<__half2*>(&gp.x));
    float2 g1 = __half22float2(*reinterpret_cast<__half2*>(&gp.y));
    float2 u0 = __half22float2(*reinterpret_cast<__half2*>(&up.x));
    float2 u1 = __half22float2(*reinterpret_cast<__half2*>(&up.y));
    uint2 o;
    o.x = pack2h(silu(g0.x) * u0.x, silu(g0.y) * u0.y);
    o.y = pack2h(silu(g1.x) * u1.x, silu(g1.y) * u1.y);
    *reinterpret_cast<uint2*>(g_h + (size_t)row * EI + c) = o;
}

// ---------------------------------------------------------------------------
// GEMM body: C[128,64] = A(fp16 rows) @ W[K][N] (f32 streamed, fragment-pack)
// 3-stage pipeline (BK=64 slab); stage issued AFTER the barrier (proven R10
// skeleton). A fragments via ldmatrix.x4, B via scalar LDS + pack.
// ---------------------------------------------------------------------------
#define TC_GEMM_BODY(A_SRC_ROW, WP, LDN, KTOT, EPILOGUE)                            \
    extern __shared__ char smc[];                                                   \
    int* s_tok = (int*)(smc + TOK_OFF);                                             \
    const int tid = threadIdx.x;                                                    \
    if (tid < BM) s_tok[tid] = g_perm[min(base + m0 + tid, NT - 1)];                \
    __syncthreads();                                                                \
    const int warp = tid >> 5, lane = tid & 31;                                     \
    const int wm = (warp & 1) * 64;                                                 \
    const int wn = (warp >> 1) * 16;                                                \
    const int grp = lane >> 2, quad = lane & 3;                                     \
    const int a_row = tid >> 3, a_ch = tid & 7;                                     \
    const int b_row = tid >> 4, b_ch = tid & 15;                                    \
    const int lm_row = wm + (lane & 15);                                            \
    const int lm_col = (lane >> 4) * 16;                                            \
    float acc[4][2][4];                                                             \
    _Pragma("unroll")                                                               \
    for (int i = 0; i < 4; i++)                                                     \
        _Pragma("unroll")                                                           \
        for (int j = 0; j < 2; j++)                                                 \
            _Pragma("unroll")                                                       \
            for (int r = 0; r < 4; r++) acc[i][j][r] = 0.f;                         \
    auto stage = [&](int kt0, int buf) {                                            \
        char* sa = smc + buf * STAGE_BYTES;                                         \
        char* sb = sa + A_BYTES;                                                    \
        _Pragma("unroll")                                                           \
        for (int i = 0; i < 4; i++) {                                               \
            int row = a_row + i * 32;                                               \
            cp_async16(sa + row * AROWB + a_ch * 16,                                \
                       A_SRC_ROW(row) + kt0 + a_ch * 8);                            \
        }                                                                           \
        _Pragma("unroll")                                                           \
        for (int i = 0; i < 4; i++) {                                               \
            int k = b_row + i * 16;                                                 \
            cp_async16(sb + k * BROWB + b_ch * 16,                                  \
                       (WP) + (size_t)(kt0 + k) * (LDN) + n0 + b_ch * 4);           \
        }                                                                           \
        CP_COMMIT();                                                                \
    };                                                                              \
    const int KT = (KTOT) / BK;                                                     \
    stage(0, 0); stage(BK, 1);                                                      \
    for (int kt = 0; kt < KT; kt++) {                                               \
        if (kt + 1 < KT) { CP_WAIT(1); } else { CP_WAIT(0); }                       \
        __syncthreads();                                                            \
        if (kt + 2 < KT) stage((kt + 2) * BK, (kt + 2) % NSTAGE);                   \
        const char*  sa  = smc + (kt % NSTAGE) * STAGE_BYTES;                       \
        const float* sbf = (const float*)(sa + A_BYTES);                            \
        const uint32_t sa_u = (uint32_t)__cvta_generic_to_shared(sa);               \
        _Pragma("unroll")                                                           \
        for (int ks = 0; ks < 4; ks++) {                                            \
            uint32_t af[4][4], bf[2][2];                                            \
            _Pragma("unroll")                                                       \
            for (int mf = 0; mf < 4; mf++)                                          \
                ldsm_x4(af[mf], sa_u + (uint32_t)((lm_row + mf * 16) * AROWB        \
                                                  + ks * 32 + lm_col));             \
            _Pragma("unroll")                                                       \
            for (int nf = 0; nf < 2; nf++) {                                        \
                int n  = wn + nf * 8 + grp;                                         \
                int k0 = ks * 16 + quad * 2;                                        \
                bf[nf][0] = pack2h(sbf[(size_t)k0 * 68 + n],                        \
                                   sbf[(size_t)(k0 + 1) * 68 + n]);                 \
                bf[nf][1] = pack2h(sbf[(size_t)(k0 + 8) * 68 + n],                  \
                                   sbf[(size_t)(k0 + 9) * 68 + n]);                 \
            }                                                                       \
            _Pragma("unroll")                                                       \
            for (int mf = 0; mf < 4; mf++)                                          \
                _Pragma("unroll")                                                   \
                for (int nf = 0; nf < 2; nf++)                                      \
                    mma_f16(acc[mf][nf], af[mf], bf[nf]);                           \
        }                                                                           \
    }                                                                               \
    const int mrem = cnt - m0;                                                      \
    _Pragma("unroll")                                                               \
    for (int mf = 0; mf < 4; mf++) {                                                \
        int r0 = wm + mf * 16 + grp;                                                \
        int r1 = r0 + 8;                                                            \
        _Pragma("unroll")                                                           \
        for (int nf = 0; nf < 2; nf++) {                                            \
            int c = n0 + wn + nf * 8 + quad * 2;                                    \
            EPILOGUE                                                                \
        }                                                                           \
    }

// GEMM1: g_gu[base+m0+r, :] = xh(token rows) @ gate_up[e]   (K=H, N=2*EI)
__global__ __launch_bounds__(256, 2)
void gemm1_kernel(const float* __restrict__ gate_up) {
    const int e   = blockIdx.z;
    const int cnt = g_cnt[e];
    const int m0  = blockIdx.y * BM;
    if (m0 >= cnt) return;
    const int base = g_off[e];
    const int n0   = blockIdx.x * BN;
    const float* Wp = gate_up + (size_t)e * H * (2 * EI);

#define A1_SRC(row) (g_xh + (size_t)s_tok[row] * H)
#define EPI1                                                                        \
    if (r0 < mrem)                                                                  \
        *reinterpret_cast<uint32_t*>(&g_gu[(size_t)(base + m0 + r0) * H + c]) =     \
            pack2h(acc[mf][nf][0], acc[mf][nf][1]);                                 \
    if (r1 < mrem)                                                                  \
        *reinterpret_cast<uint32_t*>(&g_gu[(size_t)(base + m0 + r1) * H + c]) =     \
            pack2h(acc[mf][nf][2], acc[mf][nf][3]);

    TC_GEMM_BODY(A1_SRC, Wp, 2 * EI, H, EPI1)
#undef A1_SRC
#undef EPI1
}

// GEMM2: out[tok, :] = g_h(sorted rows) @ down[e]   (K=EI, N=H)
__global__ __launch_bounds__(256, 2)
void gemm2_kernel(const float* __restrict__ down, float* __restrict__ out) {
    const int e   = blockIdx.z;
    const int cnt = g_cnt[e];
    const int m0  = blockIdx.y * BM;
    if (m0 >= cnt) return;
    const int base = g_off[e];
    const int n0   = blockIdx.x * BN;
    const float* Wp = down + (size_t)e * EI * H;

#define A2_SRC(row) (g_h + (size_t)min(base + m0 + (row), NT - 1) * EI)
#define EPI2                                                                        \
    if (r0 < mrem)                                                                  \
        *reinterpret_cast<float2*>(&out[(size_t)s_tok[r0] * H + c]) =               \
            make_float2(acc[mf][nf][0], acc[mf][nf][1]);                            \
    if (r1 < mrem)                                                                  \
        *reinterpret_cast<float2*>(&out[(size_t)s_tok[r1] * H + c]) =               \
            make_float2(acc[mf][nf][2], acc[mf][nf][3]);

    TC_GEMM_BODY(A2_SRC, Wp, H, EI, EPI2)
#undef A2_SRC
#undef EPI2
}

// ---------------------------------------------------------------------------
// Launch
// ---------------------------------------------------------------------------
extern "C" void kernel_launch(void* const* d_in, const int* in_sizes, int n_in,
                              void* d_out, int out_size) {
    const float* x         = (const float*)d_in[0];
    const int*   token_ids = (const int*)d_in[1];
    const float* gate_up   = (const float*)d_in[2];
    const float* down      = (const float*)d_in[3];
    float*       out       = (float*)d_out;

    cudaFuncSetAttribute(gemm1_kernel, cudaFuncAttributeMaxDynamicSharedMemorySize, SMEM_BYTES);
    cudaFuncSetAttribute(gemm2_kernel, cudaFuncAttributeMaxDynamicSharedMemorySize, SMEM_BYTES);

    prep_kernel<<<NXB + 1, 256>>>(x, token_ids);

    dim3 grid1(2 * EI / BN, NT / BM, NE);   // 32 x 16 x 8
    gemm1_kernel<<<grid1, 256, SMEM_BYTES>>>(gate_up);
    act_kernel<<<(NT * EI / 4) / 256, 256>>>();
    dim3 grid2(H / BN, NT / BM, NE);        // 32 x 16 x 8
    gemm2_kernel<<<grid2, 256, SMEM_BYTES>>>(down, out);
}